// round 1
// baseline (speedup 1.0000x reference)
#include <cuda_runtime.h>

// LIF_ASC recurrent spiking net: T=4096 steps, B=256 batch, N=12 neurons.
// Latency-bound serial recurrence -> 1 (batch,neuron) per lane, 2 batches/warp,
// matvec via width-16 shuffles, deep (8-step) x prefetch.

#define TT 4096
#define BB 256
#define NN 12
#define CH 8          // prefetch / unroll chunk

__device__ __forceinline__ float mul_sat(float a, float b) {
    float r;
    asm("mul.rn.sat.f32 %0, %1, %2;" : "=f"(r) : "f"(a), "f"(b));
    return r;
}

__global__ void __launch_bounds__(32, 1) lif_asc_kernel(
    const float* __restrict__ x_in,
    const float* __restrict__ w,
    const float* __restrict__ G,
    const float* __restrict__ E_L,
    const float* __restrict__ tau_m,
    const float* __restrict__ tau_s,
    const float* __restrict__ f_I,
    const int*   __restrict__ neuron_types,
    float* __restrict__ out)
{
    const int lane = threadIdx.x & 31;
    const int sub  = lane >> 4;          // which batch within the warp (0/1)
    const int n    = lane & 15;          // neuron index (active if < 12)
    const int b    = blockIdx.x * 2 + sub;
    const bool active = (n < NN);

    // Weight column for this neuron, with 0.5, neuron_types sign, and the
    // no-self-recurrence diagonal mask folded in:
    //   wc[j] = 0.5 * w[j][n] * nt[j],  wc[n] = 0
    float wc[NN];
    #pragma unroll
    for (int j = 0; j < NN; j++) {
        float wj = 0.0f;
        if (active && j != n) {
            wj = 0.5f * w[j * NN + n] * (float)neuron_types[j];
        }
        wc[j] = wj;
    }

    // Per-neuron constants (safe defaults for the 4 idle lanes per group).
    const float g  = active ? G[n]     : 1.0f;
    const float el = active ? E_L[n]   : -62.0f;
    const float tm = active ? tau_m[n] : 1.0f;
    const float ts = active ? tau_s[n] : 1.0f;
    const float fi = active ? f_I[n]   : 0.0f;

    const float thr     = 30.0f;
    const float norm_R  = (thr - el) * 1.1f;      // stop_gradient const
    const float inv_tm  = 1.0f / tm;
    const float kA      = g * el * inv_tm;        // dv = kA - kB*v + kC*I
    const float kB      = g * inv_tm;
    const float kC      = norm_R * inv_tm;
    const float invthr  = 1.0f / thr;
    const float inv_dEL = 1.0f / (thr - el);
    const float its     = 1.0f / ts;
    const float om_its  = 1.0f - its;
    const float om_f    = 1.0f - fi;

    // State
    float v = 0.0f, s = 0.0f, Ia = 0.0f;

    const long stride = (long)BB * NN;
    const float* xp = x_in + (long)b * NN + n;
    float*       op = out  + (long)b * NN + n;

    // Prime the first chunk of inputs (gain folded in).
    float xb[CH];
    #pragma unroll
    for (int k = 0; k < CH; k++)
        xb[k] = active ? (1.75f * xp[(long)k * stride]) : 0.0f;

    for (int tc = 0; tc < TT; tc += CH) {
        // Issue next chunk's loads first: >= 8-step (~650 cyc) latency cover.
        float xn[CH];
        #pragma unroll
        for (int k = 0; k < CH; k++) {
            const int tt = tc + CH + k;
            xn[k] = (tt < TT && active) ? (1.75f * xp[(long)tt * stride]) : 0.0f;
        }

        #pragma unroll
        for (int k = 0; k < CH; k++) {
            const float gx = xb[k];

            // Off-critical-path precomputes (depend only on last step's v, s).
            const float tAB  = fmaf(-kB, v, kA);     // kA - kB*v
            const float spre = s * om_its;           // s*(1 - 1/tau_s)

            // a = s + I_add; the 0.5 lives in wc.
            const float a = s + Ia;

            // Broadcast a_j within the 16-lane batch group; 4 accumulators.
            float acc0 = gx, acc1 = 0.0f, acc2 = 0.0f, acc3 = 0.0f;
            #pragma unroll
            for (int j = 0; j < NN; j += 4) {
                const float a0 = __shfl_sync(0xFFFFFFFFu, a, j + 0, 16);
                const float a1 = __shfl_sync(0xFFFFFFFFu, a, j + 1, 16);
                const float a2 = __shfl_sync(0xFFFFFFFFu, a, j + 2, 16);
                const float a3 = __shfl_sync(0xFFFFFFFFu, a, j + 3, 16);
                acc0 = fmaf(a0, wc[j + 0], acc0);
                acc1 = fmaf(a1, wc[j + 1], acc1);
                acc2 = fmaf(a2, wc[j + 2], acc2);
                acc3 = fmaf(a3, wc[j + 3], acc3);
            }
            const float I = (acc0 + acc1) + (acc2 + acc3);

            const float dv     = fmaf(I, kC, tAB);
            const float v_next = v + dv;
            const float gating = mul_sat(v_next, invthr);   // clip(v/thr,0,1)
            const float dvclip = mul_sat(dv, inv_dEL);      // clip(dv/(thr-EL),0,1)
            const float m      = gating * dvclip;
            const float s_new  = fmaf(m, its, spre);

            const bool  spiked = (v_next >= thr);
            v  = spiked ? el : v_next;
            const float spk = spiked ? fi : 0.0f;
            Ia = fmaf(Ia, om_f, spk);                       // I*(1-f) + spiked*f
            s  = s_new;

            if (active) op[(long)(tc + k) * stride] = s_new * ts;
        }

        #pragma unroll
        for (int k = 0; k < CH; k++) xb[k] = xn[k];
    }
}

extern "C" void kernel_launch(void* const* d_in, const int* in_sizes, int n_in,
                              void* d_out, int out_size) {
    const float* x_in  = (const float*)d_in[0];
    const float* w     = (const float*)d_in[1];
    const float* G     = (const float*)d_in[2];
    const float* E_L   = (const float*)d_in[3];
    const float* tau_m = (const float*)d_in[4];
    const float* tau_s = (const float*)d_in[5];
    const float* f_I   = (const float*)d_in[6];
    const int*   nt    = (const int*)d_in[7];
    float* out = (float*)d_out;

    (void)in_sizes; (void)n_in; (void)out_size;

    // 128 blocks x 32 threads: one warp per SM (single wave on 148 SMs),
    // 2 batches per warp -> all 256 batches.
    lif_asc_kernel<<<BB / 2, 32>>>(x_in, w, G, E_L, tau_m, tau_s, f_I, nt, out);
}

// round 2
// speedup vs baseline: 1.4892x; 1.4892x over previous
#include <cuda_runtime.h>

// LIF_ASC: T=4096 serial steps, B=256, N=12. Latency-chain bound.
// R2: replace shuffle matvec (SB-serialized, ~260 cyc/step) with smem
// broadcast exchange (STS + syncwarp + 3x LDS.128), fold kC and v into the
// dot accumulators, keep all state-only math off the critical path.

#define TT 4096
#define BB 256
#define NN 12
#define CH 8          // x prefetch chunk (double-buffered)

__device__ __forceinline__ float fmul_sat(float a, float b) {
    float r;
    asm("mul.rn.sat.f32 %0, %1, %2;" : "=f"(r) : "f"(a), "f"(b));
    return r;
}
__device__ __forceinline__ float ffma_sat(float a, float b, float c) {
    float r;
    asm("fma.rn.sat.f32 %0, %1, %2, %3;" : "=f"(r) : "f"(a), "f"(b), "f"(c));
    return r;
}

__global__ void __launch_bounds__(32, 1) lif_asc_kernel(
    const float* __restrict__ x_in,
    const float* __restrict__ w,
    const float* __restrict__ G,
    const float* __restrict__ E_L,
    const float* __restrict__ tau_m,
    const float* __restrict__ tau_s,
    const float* __restrict__ f_I,
    const int*   __restrict__ neuron_types,
    float* __restrict__ out)
{
    const int lane = threadIdx.x & 31;
    const int g    = lane >> 4;              // batch group within warp (0/1)
    const int n    = lane & 15;              // neuron slot (active if < 12)
    const int nc   = (n < NN) ? n : (NN - 1);// clamped neuron index
    const int b    = blockIdx.x * 2 + g;
    const bool active = (n < NN);

    // Per-neuron constants (clamped index: always real values, safe for idle lanes).
    const float gG = G[nc];
    const float el = E_L[nc];
    const float tm = tau_m[nc];
    const float ts = tau_s[nc];
    const float fi = f_I[nc];

    const float thr     = 30.0f;
    const float norm_R  = (thr - el) * 1.1f;
    const float inv_tm  = 1.0f / tm;
    const float kA      = gG * el * inv_tm;      // dv = kA - kB*v + kC*I
    const float kB      = gG * inv_tm;
    const float kC      = norm_R * inv_tm;
    const float kC175   = kC * 1.75f;            // input gain folded with kC
    const float invthr  = 1.0f / thr;
    const float inv_dEL = 1.0f / (thr - el);
    const float its     = 1.0f / ts;
    const float om_its  = 1.0f - its;
    const float om_f    = 1.0f - fi;

    // Weight column with 0.5, neuron sign, diagonal mask AND kC folded in:
    // v_next = v + tAB + sum_j wck[j]*a_j + kC175*x
    float wck[NN];
    #pragma unroll
    for (int j = 0; j < NN; j++) {
        float wj = 0.0f;
        if (active && j != n)
            wj = kC * 0.5f * w[j * NN + n] * (float)neuron_types[j];
        wck[j] = wj;
    }

    // Exchange buffers: [parity][group*16 + slot], 64B per group, double-buffered.
    __shared__ __align__(16) float buf[2][32];
    const int wr = g * 16 + n;                       // all 32 lanes distinct
    const float4* rd0 = (const float4*)&buf[0][g * 16];
    const float4* rd1 = (const float4*)&buf[1][g * 16];

    // State
    float v = 0.0f, s = 0.0f, Ia = 0.0f;

    const long stride = (long)BB * NN;
    const float* xp = x_in + (long)b * NN + nc;      // clamped: always in-bounds
    const float* op0 = out + (long)b * NN + nc;

    // Prime first chunk of x.
    float xb[CH];
    #pragma unroll
    for (int k = 0; k < CH; k++)
        xb[k] = xp[(long)k * stride];

    for (int tc = 0; tc < TT; tc += CH) {
        // Prefetch next chunk (clamped index: in-bounds, tail values unused).
        float xn[CH];
        #pragma unroll
        for (int k = 0; k < CH; k++) {
            const int tt = min(tc + CH + k, TT - 1);
            xn[k] = xp[(long)tt * stride];
        }
        float* opc = (float*)(op0 + (long)tc * stride);

        #pragma unroll
        for (int k = 0; k < CH; k++) {
            // ---- off-critical precomputes (depend only on entering state) ----
            const float tAB  = fmaf(-kB, v, kA);                 // kA - kB*v
            const float base = v + tAB;
            const float init = fmaf(xb[k], kC175, base);         // acc0 seed
            const float voff = v * inv_dEL;
            const float spre = s * om_its;
            const float iam  = Ia * om_f;

            // ---- exchange a = s + Ia across the 12 neurons of this batch ----
            const float a = s + Ia;
            buf[k & 1][wr] = a;
            __syncwarp(0xFFFFFFFFu);
            const float4* rd = (k & 1) ? rd1 : rd0;
            const float4 A0 = rd[0];
            const float4 A1 = rd[1];
            const float4 A2 = rd[2];

            // ---- dot (kC folded in wck, v+tAB+gain*x folded in acc0) ----
            float acc0 = fmaf(A0.x, wck[0], init);
            float acc1 = A0.y * wck[1];
            float acc2 = A0.z * wck[2];
            float acc3 = A0.w * wck[3];
            acc0 = fmaf(A1.x, wck[4], acc0);
            acc1 = fmaf(A1.y, wck[5], acc1);
            acc2 = fmaf(A1.z, wck[6], acc2);
            acc3 = fmaf(A1.w, wck[7], acc3);
            acc0 = fmaf(A2.x, wck[8], acc0);
            acc1 = fmaf(A2.y, wck[9], acc1);
            acc2 = fmaf(A2.z, wck[10], acc2);
            acc3 = fmaf(A2.w, wck[11], acc3);
            const float v_next = (acc0 + acc1) + (acc2 + acc3);

            // ---- pointwise (short path to a' for next step) ----
            const float gating = fmul_sat(v_next, invthr);           // clip(v/thr)
            const float dvclip = ffma_sat(v_next, inv_dEL, -voff);   // clip(dv/(thr-EL))
            const bool  spiked = (v_next >= thr);
            const float m      = gating * dvclip;
            const float s2     = fmaf(m, its, spre);
            const float spk    = spiked ? fi : 0.0f;
            const float Ia2    = iam + spk;
            v  = spiked ? el : v_next;
            s  = s2;
            Ia = Ia2;

            if (active) opc[(long)k * stride] = s2 * ts;
        }

        #pragma unroll
        for (int k = 0; k < CH; k++) xb[k] = xn[k];
    }
}

extern "C" void kernel_launch(void* const* d_in, const int* in_sizes, int n_in,
                              void* d_out, int out_size) {
    const float* x_in  = (const float*)d_in[0];
    const float* w     = (const float*)d_in[1];
    const float* G     = (const float*)d_in[2];
    const float* E_L   = (const float*)d_in[3];
    const float* tau_m = (const float*)d_in[4];
    const float* tau_s = (const float*)d_in[5];
    const float* f_I   = (const float*)d_in[6];
    const int*   nt    = (const int*)d_in[7];
    float* out = (float*)d_out;

    (void)in_sizes; (void)n_in; (void)out_size;

    // 128 blocks x 1 warp: one warp per SM, 2 batches per warp.
    lif_asc_kernel<<<BB / 2, 32>>>(x_in, w, G, E_L, tau_m, tau_s, f_I, nt, out);
}

// round 4
// speedup vs baseline: 1.6263x; 1.0921x over previous
#include <cuda_runtime.h>

// LIF_ASC: T=4096 serial steps, B=256, N=12. Pure dependency-chain bound.
// R4 (= R3 resubmit + micro-cuts): no WARPSYNC in the STS->LDS exchange
// (branchless converged warp), single-op saturate spike indicator on the
// a-chain (a ready at v_next+12), fma-folded dot seed, constant-immediate
// prefetch/store addressing.

#define TT 4096
#define BB 256
#define NN 12
#define CH 8          // x prefetch chunk

__device__ __forceinline__ float fmul_sat(float a, float b) {
    float r;
    asm("mul.rn.sat.f32 %0, %1, %2;" : "=f"(r) : "f"(a), "f"(b));
    return r;
}
__device__ __forceinline__ float ffma_sat(float a, float b, float c) {
    float r;
    asm("fma.rn.sat.f32 %0, %1, %2, %3;" : "=f"(r) : "f"(a), "f"(b), "f"(c));
    return r;
}

__global__ void __launch_bounds__(32, 1) lif_asc_kernel(
    const float* __restrict__ x_in,
    const float* __restrict__ w,
    const float* __restrict__ G,
    const float* __restrict__ E_L,
    const float* __restrict__ tau_m,
    const float* __restrict__ tau_s,
    const float* __restrict__ f_I,
    const int*   __restrict__ neuron_types,
    float* __restrict__ out)
{
    const int lane = threadIdx.x & 31;
    const int g    = lane >> 4;               // batch group within warp (0/1)
    const int n    = lane & 15;               // neuron slot (active if < 12)
    const int nc   = (n < NN) ? n : (NN - 1); // clamped neuron index
    const int b    = blockIdx.x * 2 + g;
    const bool active = (n < NN);

    // Per-neuron constants (clamped: idle lanes get neuron 11's values).
    const float gG = G[nc];
    const float el = E_L[nc];
    const float tm = tau_m[nc];
    const float ts = tau_s[nc];
    const float fi = f_I[nc];

    const float thr     = 30.0f;
    const float norm_R  = (thr - el) * 1.1f;
    const float inv_tm  = 1.0f / tm;
    const float kA      = gG * el * inv_tm;   // dv = kA - kB*v + kC*I
    const float kB      = gG * inv_tm;
    const float kV      = 1.0f - kB;          // v + tAB = kA + kV*v
    const float kC      = norm_R * inv_tm;
    const float kC175   = kC * 1.75f;         // input gain folded with kC
    const float invthr  = 1.0f / thr;
    const float inv_dEL = 1.0f / (thr - el);
    const float its     = 1.0f / ts;
    const float om_its  = 1.0f - its;
    const float om_f    = 1.0f - fi;
    const float BIG     = 1e30f;
    const float nThrBIG = -thr * BIG;         // spk01 = sat(fma(v_next,BIG,nThrBIG))

    // Weight column with 0.5, sign, diagonal mask and kC folded in.
    float wck[NN];
    #pragma unroll
    for (int j = 0; j < NN; j++) {
        float wj = 0.0f;
        if (active && j != n)
            wj = kC * 0.5f * w[j * NN + n] * (float)neuron_types[j];
        wck[j] = wj;
    }

    // Double-buffered exchange: [parity][group*16 + slot].
    __shared__ __align__(16) float buf[2][32];
    volatile float* wp0 = &buf[0][g * 16 + n];
    volatile float* wp1 = &buf[1][g * 16 + n];
    const float4* rd0 = (const float4*)&buf[0][g * 16];
    const float4* rd1 = (const float4*)&buf[1][g * 16];

    // State (v, s, Ia off-chain; a = s + Ia is the chain variable).
    float v = 0.0f, s = 0.0f, Ia = 0.0f, a = 0.0f;

    const int stride = BB * NN;               // elements per time step
    const float* xp = x_in + b * NN + nc;     // always in-bounds (clamped n)
    float*       op = out  + b * NN + nc;

    // Prime first chunk.
    float xb[CH];
    #pragma unroll
    for (int k = 0; k < CH; k++)
        xb[k] = xp[k * stride];

    for (int tc = 0; tc < TT; tc += CH) {
        // Prefetch next chunk; clamp the BASE so unrolled imm offsets stay
        // in-bounds (tail re-reads the last chunk, values unused).
        const int nb = min(tc + CH, TT - CH);
        const float* xpn = xp + nb * stride;
        float xn[CH];
        #pragma unroll
        for (int k = 0; k < CH; k++)
            xn[k] = xpn[k * stride];

        float* opc = op + tc * stride;

        #pragma unroll
        for (int k = 0; k < CH; k++) {
            // ---- exchange a across the 12 neurons (no barrier: branchless
            //      converged warp, smem ops execute in program order) ----
            if (k & 1) *wp1 = a; else *wp0 = a;
            asm volatile("" ::: "memory");
            const float4* rd = (k & 1) ? rd1 : rd0;
            const float4 A0 = rd[0];
            const float4 A1 = rd[1];
            const float4 A2 = rd[2];

            // ---- off-chain precomputes (entering state) ----
            const float init = fmaf(xb[k], kC175, fmaf(v, kV, kA)); // dot seed
            const float voff = v * inv_dEL;
            const float spre = s * om_its;
            const float iam  = Ia * om_f;
            const float P    = spre + iam;                   // a-chain base

            // ---- dot: v_next = init + sum_j wck[j]*a_j ----
            float acc0 = fmaf(A0.x, wck[0], init);
            float acc1 = A0.y * wck[1];
            float acc2 = A0.z * wck[2];
            float acc3 = A0.w * wck[3];
            acc0 = fmaf(A1.x, wck[4], acc0);
            acc1 = fmaf(A1.y, wck[5], acc1);
            acc2 = fmaf(A1.z, wck[6], acc2);
            acc3 = fmaf(A1.w, wck[7], acc3);
            acc0 = fmaf(A2.x, wck[8], acc0);
            acc1 = fmaf(A2.y, wck[9], acc1);
            acc2 = fmaf(A2.z, wck[10], acc2);
            acc3 = fmaf(A2.w, wck[11], acc3);
            const float v_next = (acc0 + acc1) + (acc2 + acc3);

            // ---- chain pointwise: a(t+1) at v_next+12 ----
            const float gating = fmul_sat(v_next, invthr);           // +4
            const float dvclip = ffma_sat(v_next, inv_dEL, -voff);   // +4
            const float spk01  = ffma_sat(v_next, BIG, nThrBIG);     // +4 (1 iff spiked)
            const float m      = gating * dvclip;                    // +8
            const float Pspk   = fmaf(spk01, fi, P);                 // +8
            a = fmaf(m, its, Pspk);                                  // +12

            // ---- off-chain state + output ----
            const bool spiked = (v_next >= thr);
            v  = spiked ? el : v_next;
            Ia = iam + (spiked ? fi : 0.0f);
            const float s2 = fmaf(m, its, spre);
            s  = s2;
            if (active) opc[k * stride] = s2 * ts;
        }

        #pragma unroll
        for (int k = 0; k < CH; k++) xb[k] = xn[k];
    }
}

extern "C" void kernel_launch(void* const* d_in, const int* in_sizes, int n_in,
                              void* d_out, int out_size) {
    const float* x_in  = (const float*)d_in[0];
    const float* w     = (const float*)d_in[1];
    const float* G     = (const float*)d_in[2];
    const float* E_L   = (const float*)d_in[3];
    const float* tau_m = (const float*)d_in[4];
    const float* tau_s = (const float*)d_in[5];
    const float* f_I   = (const float*)d_in[6];
    const int*   nt    = (const int*)d_in[7];
    float* out = (float*)d_out;

    (void)in_sizes; (void)n_in; (void)out_size;

    // 128 blocks x 1 warp: one warp per SM, 2 batches per warp.
    lif_asc_kernel<<<BB / 2, 32>>>(x_in, w, G, E_L, tau_m, tau_s, f_I, nt, out);
}